// round 1
// baseline (speedup 1.0000x reference)
#include <cuda_runtime.h>
#include <math.h>

#define SEQ 16384
#define D 1024
#define D4 (D / 4)          // 256 float4 per row
#define NWARPROWS (2 * SEQ) // one warp per (head,row)

__device__ float g_logits[2 * SEQ];
__device__ float g_stats[4]; // m1, s1, m2, s2

// ---------------------------------------------------------------------------
// Kernel 1: logits[head][row] = dot(w[head], G[head][row])
// One warp per row. Each lane reads 8 float4 (stride 32 across warp = 128B
// coalesced). Weights are L2/L1 resident after first touch.
// ---------------------------------------------------------------------------
__global__ void __launch_bounds__(256) logits_kernel(
    const float4* __restrict__ g1, const float4* __restrict__ g2,
    const float4* __restrict__ w1, const float4* __restrict__ w2)
{
    int gwarp = (blockIdx.x * blockDim.x + threadIdx.x) >> 5;
    int lane  = threadIdx.x & 31;
    int head  = gwarp >> 14;        // 16384 warps per head
    int row   = gwarp & (SEQ - 1);

    const float4* __restrict__ g = (head == 0) ? g1 : g2;
    const float4* __restrict__ w = (head == 0) ? w1 : w2;
    const float4* __restrict__ grow = g + (size_t)row * D4;

    float acc = 0.0f;
#pragma unroll
    for (int i = 0; i < 8; i++) {
        float4 a = __ldg(&grow[lane + i * 32]);
        float4 b = __ldg(&w[lane + i * 32]);
        acc = fmaf(a.x, b.x, acc);
        acc = fmaf(a.y, b.y, acc);
        acc = fmaf(a.z, b.z, acc);
        acc = fmaf(a.w, b.w, acc);
    }
#pragma unroll
    for (int o = 16; o > 0; o >>= 1)
        acc += __shfl_down_sync(0xffffffffu, acc, o);

    if (lane == 0)
        g_logits[head * SEQ + row] = acc;
}

// ---------------------------------------------------------------------------
// Kernel 2: per-head online softmax reduction (max m, sum s = Σ exp(x - m)).
// One block per head.
// ---------------------------------------------------------------------------
__global__ void __launch_bounds__(512) stats_kernel()
{
    int head = blockIdx.x;
    const float* __restrict__ lg = g_logits + head * SEQ;

    float m = -INFINITY, s = 0.0f;
    for (int i = threadIdx.x; i < SEQ; i += 512) {
        float x = lg[i];
        float nm = fmaxf(m, x);
        s = s * __expf(m - nm) + __expf(x - nm);
        m = nm;
    }

    __shared__ float sm[512];
    __shared__ float ss[512];
    sm[threadIdx.x] = m;
    ss[threadIdx.x] = s;
    __syncthreads();

    for (int stride = 256; stride > 0; stride >>= 1) {
        if (threadIdx.x < stride) {
            float m2 = sm[threadIdx.x + stride];
            float s2 = ss[threadIdx.x + stride];
            float M  = fmaxf(sm[threadIdx.x], m2);
            ss[threadIdx.x] = ss[threadIdx.x] * __expf(sm[threadIdx.x] - M)
                            + s2 * __expf(m2 - M);
            sm[threadIdx.x] = M;
        }
        __syncthreads();
    }

    if (threadIdx.x == 0) {
        g_stats[head * 2 + 0] = sm[0];
        g_stats[head * 2 + 1] = ss[0];
    }
}

// ---------------------------------------------------------------------------
// Kernel 3: out[i] = exp(logit[i] - m) / s
// ---------------------------------------------------------------------------
__global__ void __launch_bounds__(256) norm_kernel(float* __restrict__ out)
{
    int i = blockIdx.x * blockDim.x + threadIdx.x;
    int head = i >> 14;
    float m = g_stats[head * 2 + 0];
    float inv_s = 1.0f / g_stats[head * 2 + 1];
    out[i] = __expf(g_logits[i] - m) * inv_s;
}

extern "C" void kernel_launch(void* const* d_in, const int* in_sizes, int n_in,
                              void* d_out, int out_size)
{
    const float4* g1 = (const float4*)d_in[0]; // G_M1 [SEQ, D]
    const float4* g2 = (const float4*)d_in[1]; // G_M2 [SEQ, D]
    const float4* w1 = (const float4*)d_in[2]; // wp1  [1, D]
    const float4* w2 = (const float4*)d_in[3]; // wp2  [1, D]
    float* out = (float*)d_out;                // [2, SEQ] (p1_pred, p2_pred)

    // 32768 warps, 8 warps/block -> 4096 blocks
    logits_kernel<<<NWARPROWS / 8, 256>>>(g1, g2, w1, w2);
    stats_kernel<<<2, 512>>>();
    norm_kernel<<<(2 * SEQ) / 256, 256>>>(out);
}